// round 6
// baseline (speedup 1.0000x reference)
#include <cuda_runtime.h>
#include <cstddef>

#define N_USER 100000
#define N_ITEM 100000
#define N_EDGE 1000000
#define D      64
#define NT     (N_USER + N_ITEM)
#define NBLK   ((N_USER + 255) / 256)     // 391 blocks per relation (N_USER == N_ITEM)
#define XPAD   68                         // smem row stride in floats (16B-aligned, low conflict)

// ---------------------------------------------------------------------------
// Scratch (static device globals — no allocation allowed)
// deg/off/cnt regions: [0, N_USER) = user dsts, [N_USER, NT) = item dsts
// elist: relation A (dst=item) in [0, N_EDGE), relation B (dst=user) in [N_EDGE, 2*N_EDGE)
// ---------------------------------------------------------------------------
__device__ int g_deg[NT];
__device__ int g_off[NT];
__device__ int g_cnt[NT];
__device__ int g_elist[2 * N_EDGE];
__device__ int g_cursor[2];

// packed f32x2 helpers
__device__ __forceinline__ unsigned long long ffma2(unsigned long long a,
                                                    unsigned long long b,
                                                    unsigned long long c) {
    unsigned long long d;
    asm("fma.rn.f32x2 %0, %1, %2, %3;" : "=l"(d) : "l"(a), "l"(b), "l"(c));
    return d;
}
__device__ __forceinline__ unsigned long long pack2(float a) {
    unsigned long long r;
    asm("mov.b64 %0, {%1, %1};" : "=l"(r) : "f"(a));
    return r;
}
__device__ __forceinline__ void unpack2(unsigned long long v, float& lo, float& hi) {
    asm("mov.b64 {%0, %1}, %2;" : "=f"(lo), "=f"(hi) : "l"(v));
}

// ---------------------------------------------------------------------------
// 1) zero metadata
// ---------------------------------------------------------------------------
__global__ void zero_meta_kernel() {
    int i = blockIdx.x * blockDim.x + threadIdx.x;
    if (i < NT) { g_deg[i] = 0; g_cnt[i] = 0; }
    if (i < 2) g_cursor[i] = 0;
}

// ---------------------------------------------------------------------------
// 2) degree count (both relations fused)
// ---------------------------------------------------------------------------
__global__ void count_kernel(const int* __restrict__ dst_item,   // dst_clicks (item ids)
                             const int* __restrict__ dst_user) { // dst_clicked_by (user ids)
    int e = blockIdx.x * blockDim.x + threadIdx.x;
    if (e >= N_EDGE) return;
    atomicAdd(&g_deg[N_USER + __ldg(dst_item + e)], 1);
    atomicAdd(&g_deg[__ldg(dst_user + e)], 1);
}

// ---------------------------------------------------------------------------
// 3) segment offsets for BOTH regions in one launch:
//    blocks [0, NBLK)      -> user region (base 0,        cursor rel 1)
//    blocks [NBLK, 2*NBLK) -> item region (base N_USER,   cursor rel 0)
//    per-block scan + bump allocator (segment order irrelevant)
// ---------------------------------------------------------------------------
__global__ __launch_bounds__(256) void offsets_kernel() {
    int blk = blockIdx.x;
    bool user = blk < NBLK;
    int base = user ? 0 : N_USER;
    int rel  = user ? 1 : 0;
    int bloc = user ? blk : blk - NBLK;

    int tid = threadIdx.x;
    int i = bloc * 256 + tid;
    int lane = tid & 31, wid = tid >> 5;

    int v = (i < N_USER) ? g_deg[base + i] : 0;   // N_USER == N_ITEM

    int x = v;
#pragma unroll
    for (int s = 1; s < 32; s <<= 1) {
        int y = __shfl_up_sync(0xFFFFFFFFu, x, s);
        if (lane >= s) x += y;
    }

    __shared__ int wsum[8];
    __shared__ int blockBase;
    if (lane == 31) wsum[wid] = x;
    __syncthreads();

    if (wid == 0) {
        int s = (lane < 8) ? wsum[lane] : 0;
#pragma unroll
        for (int d2 = 1; d2 < 8; d2 <<= 1) {
            int y = __shfl_up_sync(0xFFFFFFFFu, s, d2);
            if (lane >= d2) s += y;
        }
        if (lane < 8) wsum[lane] = s;
        if (lane == 7) blockBase = atomicAdd(&g_cursor[rel], s);
    }
    __syncthreads();

    if (i < N_USER) {
        int warpBase = (wid > 0) ? wsum[wid - 1] : 0;
        g_off[base + i] = blockBase + warpBase + (x - v);
    }
}

// ---------------------------------------------------------------------------
// 4) fill edge lists (both relations fused)
// ---------------------------------------------------------------------------
__global__ void fill_kernel(const int* __restrict__ src_clicks,
                            const int* __restrict__ dst_clicks,
                            const int* __restrict__ src_cb,
                            const int* __restrict__ dst_cb) {
    int e = blockIdx.x * blockDim.x + threadIdx.x;
    if (e >= N_EDGE) return;
    {   // relation A: user -> item (dst region offset N_USER, elist region 0)
        int d = N_USER + __ldg(dst_clicks + e);
        int p = atomicAdd(&g_cnt[d], 1);
        g_elist[__ldg(&g_off[d]) + p] = __ldg(src_clicks + e);
    }
    {   // relation B: item -> user (dst region 0, elist region N_EDGE)
        int d = __ldg(dst_cb + e);
        int p = atomicAdd(&g_cnt[d], 1);
        g_elist[N_EDGE + __ldg(&g_off[d]) + p] = __ldg(src_cb + e);
    }
}

// ---------------------------------------------------------------------------
// 5) FUSED gather-mean + linear:
//    Phase A: half-warp per dst gathers neighbor rows (float4/lane), mean -> smem
//    Phase B: thread-per-row GEMV from smem (broadcast W^T, packed f32x2 FMA)
//    blocks [0, NBLK): user dsts  |  blocks [NBLK, 2*NBLK): item dsts
// ---------------------------------------------------------------------------
__global__ __launch_bounds__(256) void fused_kernel(
        const float* __restrict__ feat_user, const float* __restrict__ feat_item,
        const float* __restrict__ W_clicks,  const float* __restrict__ b_clicks,
        const float* __restrict__ W_cb,      const float* __restrict__ b_cb,
        float* __restrict__ out) {
    extern __shared__ float smem[];
    float* Wt = smem;              // [64*64], Wt[k*64 + j] = W[j*64 + k]
    float* bs = smem + 4096;       // [64]
    float* X  = smem + 4160;       // [256][XPAD]

    int blk = blockIdx.x;
    bool user = blk < NBLK;        // user dsts receive from items via clicked_by
    const float* feat = user ? feat_item : feat_user;
    const float* W    = user ? W_cb      : W_clicks;
    const float* bias = user ? b_cb      : b_clicks;
    int deg_off    = user ? 0 : N_USER;
    int elist_base = user ? N_EDGE : 0;
    float* outT    = out + (user ? 0 : (size_t)N_USER * D);
    int blockBase  = (user ? blk : blk - NBLK) * 256;
    const int n_dst = N_USER;      // == N_ITEM

    int tid = threadIdx.x;

    // stage W^T and bias
    for (int i = tid; i < D * D; i += 256) {
        int j = i >> 6, k = i & 63;
        Wt[k * D + j] = W[i];
    }
    if (tid < D) bs[tid] = bias[tid];

    // ---------------- Phase A: gather means into smem ----------------
    {
        int wid = tid >> 5, lane = tid & 31;
        int g = lane >> 4, sub = lane & 15;   // half-warp per dst, float4 per lane
#pragma unroll 1
        for (int it = 0; it < 16; it++) {
            int l = wid * 32 + it * 2 + g;
            int row = blockBase + l;
            if (row < n_dst) {
                int deg = __ldg(&g_deg[deg_off + row]);
                const int* el = g_elist + elist_base + __ldg(&g_off[deg_off + row]);
                float ax = 0.f, ay = 0.f, az = 0.f, aw = 0.f;
                int e = 0;
                for (; e + 4 <= deg; e += 4) {
                    int s0 = __ldg(el + e);
                    int s1 = __ldg(el + e + 1);
                    int s2 = __ldg(el + e + 2);
                    int s3 = __ldg(el + e + 3);
                    float4 v0 = __ldg(reinterpret_cast<const float4*>(feat + (size_t)s0 * D) + sub);
                    float4 v1 = __ldg(reinterpret_cast<const float4*>(feat + (size_t)s1 * D) + sub);
                    float4 v2 = __ldg(reinterpret_cast<const float4*>(feat + (size_t)s2 * D) + sub);
                    float4 v3 = __ldg(reinterpret_cast<const float4*>(feat + (size_t)s3 * D) + sub);
                    ax += (v0.x + v1.x) + (v2.x + v3.x);
                    ay += (v0.y + v1.y) + (v2.y + v3.y);
                    az += (v0.z + v1.z) + (v2.z + v3.z);
                    aw += (v0.w + v1.w) + (v2.w + v3.w);
                }
                for (; e < deg; e++) {
                    int s0 = __ldg(el + e);
                    float4 v0 = __ldg(reinterpret_cast<const float4*>(feat + (size_t)s0 * D) + sub);
                    ax += v0.x; ay += v0.y; az += v0.z; aw += v0.w;
                }
                float inv = deg > 0 ? 1.f / (float)deg : 0.f;
                float4 m; m.x = ax * inv; m.y = ay * inv; m.z = az * inv; m.w = aw * inv;
                *reinterpret_cast<float4*>(X + l * XPAD + 4 * sub) = m;
            }
        }
    }
    __syncthreads();

    // ---------------- Phase B: per-row GEMV from smem ----------------
    int row = blockBase + tid;
    if (row >= n_dst) return;

    const float* x = X + tid * XPAD;

    unsigned long long acc[D / 2];
#pragma unroll
    for (int j = 0; j < D / 2; j++) acc[j] = 0ull;

#pragma unroll 1
    for (int k4 = 0; k4 < D / 4; k4++) {
        float4 xv = *reinterpret_cast<const float4*>(x + 4 * k4);
        float xs[4] = {xv.x, xv.y, xv.z, xv.w};
#pragma unroll
        for (int kk = 0; kk < 4; kk++) {
            unsigned long long xk2 = pack2(xs[kk]);
            const ulonglong2* wrow =
                reinterpret_cast<const ulonglong2*>(Wt + (k4 * 4 + kk) * D);
#pragma unroll
            for (int j4 = 0; j4 < D / 4; j4++) {
                ulonglong2 wv = wrow[j4];
                acc[2 * j4 + 0] = ffma2(xk2, wv.x, acc[2 * j4 + 0]);
                acc[2 * j4 + 1] = ffma2(xk2, wv.y, acc[2 * j4 + 1]);
            }
        }
    }

    int dg = __ldg(&g_deg[deg_off + row]);
    float bm = dg > 0 ? 1.f : 0.f;

    float* o = outT + (size_t)row * D;
#pragma unroll
    for (int j4 = 0; j4 < D / 4; j4++) {
        float l0, h0, l1, h1;
        unpack2(acc[2 * j4 + 0], l0, h0);
        unpack2(acc[2 * j4 + 1], l1, h1);
        float4 y;
        y.x = l0 + bs[4 * j4 + 0] * bm;
        y.y = h0 + bs[4 * j4 + 1] * bm;
        y.z = l1 + bs[4 * j4 + 2] * bm;
        y.w = h1 + bs[4 * j4 + 3] * bm;
        *reinterpret_cast<float4*>(o + 4 * j4) = y;
    }
}

// ---------------------------------------------------------------------------
// Launch
// ---------------------------------------------------------------------------
extern "C" void kernel_launch(void* const* d_in, const int* in_sizes, int n_in,
                              void* d_out, int out_size) {
    const float* feat_user  = (const float*)d_in[0];
    const float* feat_item  = (const float*)d_in[1];
    const int*   src_clicks = (const int*)d_in[2];   // user ids
    const int*   dst_clicks = (const int*)d_in[3];   // item ids
    const int*   src_cb     = (const int*)d_in[4];   // item ids
    const int*   dst_cb     = (const int*)d_in[5];   // user ids
    const float* W_clicks   = (const float*)d_in[6];
    const float* b_clicks   = (const float*)d_in[7];
    const float* W_cb       = (const float*)d_in[8];
    const float* b_cb       = (const float*)d_in[9];

    float* out = (float*)d_out;

    const int FUSED_SMEM = (4096 + 64 + 256 * XPAD) * 4;   // 86272 B
    cudaFuncSetAttribute(fused_kernel,
                         cudaFuncAttributeMaxDynamicSharedMemorySize, FUSED_SMEM);

    // 1) zero metadata
    zero_meta_kernel<<<(NT + 255) / 256, 256>>>();

    // 2) degree count (both relations)
    count_kernel<<<(N_EDGE + 255) / 256, 256>>>(dst_clicks, dst_cb);

    // 3) segment offsets (both regions, one launch)
    offsets_kernel<<<2 * NBLK, 256>>>();

    // 4) fill edge lists
    fill_kernel<<<(N_EDGE + 255) / 256, 256>>>(src_clicks, dst_clicks, src_cb, dst_cb);

    // 5) fused gather-mean + linear (both relations, one launch)
    fused_kernel<<<2 * NBLK, 256, FUSED_SMEM>>>(feat_user, feat_item,
                                                W_clicks, b_clicks,
                                                W_cb, b_cb, out);
}